// round 8
// baseline (speedup 1.0000x reference)
#include <cuda_runtime.h>

#define IN_DIM   8192
#define OUT_DIM  16384
#define TOPK     327

// ---------------- device scratch (no allocations allowed) ----------------
__device__ int g_overlap[OUT_DIM];
__device__ int g_active[IN_DIM];
__device__ int g_nactive;

// ---------------- kernel 1: zero overlap + counter ----------------
__global__ void k_init() {
    int i = blockIdx.x * blockDim.x + threadIdx.x;
    if (i < OUT_DIM) g_overlap[i] = 0;
    if (i == 0) g_nactive = 0;
}

// ---------------- kernel 2: compact active rows ----------------
// Order of g_active is arbitrary (atomic), but the GEMV sum over rows is
// order-invariant in int32, so the result is deterministic.
__global__ void k_compact(const int* __restrict__ x) {
    int t = threadIdx.x;
    for (int r = t; r < IN_DIM; r += blockDim.x) {
        if (x[r] != 0) {
            int pos = atomicAdd(&g_nactive, 1);
            g_active[pos] = r;
        }
    }
}

// ---------------- kernel 3: binarized GEMV over active rows ----------------
// grid.x = 16 column tiles (1024 cols each), grid.y = 64 row splits (128 rows
// of the compacted active list each). 256 threads, 4 columns/thread (float4).
#define ROWS_PER_SPLIT 128
__global__ void __launch_bounds__(256) k_gemv(const float* __restrict__ p) {
    __shared__ int srows[ROWS_PER_SPLIT];
    int t = threadIdx.x;
    int na = g_nactive;
    int base = blockIdx.y * ROWS_PER_SPLIT;
    int cnt = na - base;
    if (cnt <= 0) return;
    if (cnt > ROWS_PER_SPLIT) cnt = ROWS_PER_SPLIT;
    if (t < cnt) srows[t] = g_active[base + t];
    __syncthreads();

    int col = blockIdx.x * 1024 + t * 4;
    int a0 = 0, a1 = 0, a2 = 0, a3 = 0;

    #pragma unroll 4
    for (int r = 0; r < cnt; r++) {
        int row = srows[r];
        const float4 v = __ldg(reinterpret_cast<const float4*>(
            p + (size_t)row * OUT_DIM + col));
        // jnp.round is half-to-even: round(0.5)=0, so connection = (p > 0.5)
        a0 += (v.x > 0.5f);
        a1 += (v.y > 0.5f);
        a2 += (v.z > 0.5f);
        a3 += (v.w > 0.5f);
    }

    atomicAdd(&g_overlap[col + 0], a0);
    atomicAdd(&g_overlap[col + 1], a1);
    atomicAdd(&g_overlap[col + 2], a2);
    atomicAdd(&g_overlap[col + 3], a3);
}

// ---------------- kernel 4: exact top-K with stable tie-break ----------------
// Single block, 1024 threads. Histogram over overlap values (0..8192),
// find threshold T s.t. count(>T) <= K <= count(>=T); select all >T plus the
// lowest-index (K - count(>T)) elements equal to T (matches jax.lax.top_k).
#define NBINS 9216   // 1024 * 9 >= 8193
__global__ void __launch_bounds__(1024) k_topk(float* __restrict__ out) {
    __shared__ int hist[NBINS];
    __shared__ int scan[1024];
    __shared__ int sT;
    __shared__ int sNat;

    int t = threadIdx.x;

    for (int i = t; i < NBINS; i += 1024) hist[i] = 0;
    __syncthreads();

    for (int i = t; i < OUT_DIM; i += 1024)
        atomicAdd(&hist[g_overlap[i]], 1);
    __syncthreads();

    // local sum over this thread's 9 bins
    int b0 = t * 9;
    int lsum = 0;
    #pragma unroll
    for (int j = 0; j < 9; j++) lsum += hist[b0 + j];
    scan[t] = lsum;
    __syncthreads();

    // inclusive Hillis-Steele scan over 1024 partials
    for (int off = 1; off < 1024; off <<= 1) {
        int v = (t >= off) ? scan[t - off] : 0;
        __syncthreads();
        scan[t] += v;
        __syncthreads();
    }
    int prefix = (t == 0) ? 0 : scan[t - 1];   // exclusive prefix (count of values in lower bins)
    __syncthreads();

    // find threshold bin: prefix(T) <= CUT < prefix(T)+hist[T]
    const int CUT = OUT_DIM - TOPK;            // 16057
    {
        int run = prefix;
        #pragma unroll
        for (int j = 0; j < 9; j++) {
            int h = hist[b0 + j];
            if (run <= CUT && run + h > CUT) {
                sT = b0 + j;
                // count strictly greater than T = OUT_DIM - (run + h)
                sNat = TOPK - (OUT_DIM - (run + h));
            }
            run += h;
        }
    }
    __syncthreads();
    const int T   = sT;
    const int nat = sNat;   // how many '== T' elements to take (lowest indices)
    __syncthreads();

    // ordered tie ranking: each thread owns 16 contiguous elements
    int e0 = t * 16;
    int ov[16];
    int c = 0;
    #pragma unroll
    for (int j = 0; j < 16; j++) {
        ov[j] = g_overlap[e0 + j];
        c += (ov[j] == T);
    }
    scan[t] = c;
    __syncthreads();
    for (int off = 1; off < 1024; off <<= 1) {
        int v = (t >= off) ? scan[t - off] : 0;
        __syncthreads();
        scan[t] += v;
        __syncthreads();
    }
    int rank = (t == 0) ? 0 : scan[t - 1];     // # of '== T' elements before my chunk
    __syncthreads();

    #pragma unroll
    for (int j = 0; j < 16; j++) {
        float o;
        if (ov[j] > T) {
            o = 1.0f;
        } else if (ov[j] == T) {
            o = (rank < nat) ? 1.0f : 0.0f;
            rank++;
        } else {
            o = 0.0f;
        }
        out[e0 + j] = o;
    }
}

// ---------------- launch ----------------
extern "C" void kernel_launch(void* const* d_in, const int* in_sizes, int n_in,
                              void* d_out, int out_size) {
    const int*   x;
    const float* p;
    if (in_sizes[0] == IN_DIM) {
        x = (const int*)d_in[0];
        p = (const float*)d_in[1];
    } else {
        x = (const int*)d_in[1];
        p = (const float*)d_in[0];
    }

    k_init<<<(OUT_DIM + 1023) / 1024, 1024>>>();
    k_compact<<<1, 1024>>>(x);
    k_gemv<<<dim3(16, 64), 256>>>(p);
    k_topk<<<1, 1024>>>((float*)d_out);
}